// round 2
// baseline (speedup 1.0000x reference)
#include <cuda_runtime.h>
#include <cuda_bf16.h>
#include <cstdint>

// Cutmix:
//   wave  [B=128, L=160000] f32
//   onehot[B=128, C=128]    f32
//   lam   [B] f32, perm [B] i32, dec [B] f32, start [B] i32
// Output: wave_mix [B,L] followed by label_out [B,C], both f32, concatenated.

static constexpr int B = 128;
static constexpr int L = 160000;
static constexpr int C = 128;
static constexpr int F4_PER_ROW = L / 4;   // 40000

__global__ __launch_bounds__(256)
void cutmix_wave_kernel(const float* __restrict__ wave,
                        const float* __restrict__ lam,
                        const int*   __restrict__ perm,
                        const float* __restrict__ dec,
                        const int*   __restrict__ start,
                        float* __restrict__ out)
{
    const int b = blockIdx.y;
    const int j = blockIdx.x * blockDim.x + threadIdx.x;   // float4 index within row
    if (j >= F4_PER_ROW) return;

    // Per-row scalars — uniform across the CTA.
    const float lam_b  = __ldg(&lam[b]);
    const int   s      = __ldg(&start[b]);
    const int   p      = __ldg(&perm[b]);
    const bool  active = (__ldg(&dec[b]) == 1.0f);
    // crop_len exactly as reference: ((1.0f - lam) * L) truncated to int32
    const int crop_len = (int)((1.0f - lam_b) * (float)L);
    const int e = s + crop_len;            // [s, e) is the crop window

    const int pos = j * 4;
    const float4* __restrict__ own_row  = (const float4*)(wave + (size_t)b * L);
    const float4* __restrict__ perm_row = (const float4*)(wave + (size_t)p * L);
    float4* __restrict__ out_row        = (float4*)(out  + (size_t)b * L);

    const bool outside = !active || e <= pos || s >= pos + 4;
    const bool inside  = active && s <= pos && pos + 4 <= e;

    float4 v;
    if (outside) {
        v = own_row[j];                    // bulk path 1: plain copy
    } else if (inside) {
        v = perm_row[j];                   // bulk path 2: copy from permuted row
    } else {
        // straddles a crop boundary (<=2 float4 per row): per-element select
        const float4 a = own_row[j];
        const float4 m = perm_row[j];
        v.x = (pos + 0 >= s && pos + 0 < e) ? m.x : a.x;
        v.y = (pos + 1 >= s && pos + 1 < e) ? m.y : a.y;
        v.z = (pos + 2 >= s && pos + 2 < e) ? m.z : a.z;
        v.w = (pos + 3 >= s && pos + 3 < e) ? m.w : a.w;
    }
    out_row[j] = v;
}

__global__ __launch_bounds__(128)
void cutmix_label_kernel(const float* __restrict__ onehot,
                         const float* __restrict__ lam,
                         const int*   __restrict__ perm,
                         const float* __restrict__ dec,
                         float* __restrict__ out_label)
{
    const int b = blockIdx.x;
    const int c = threadIdx.x;        // C == 128 == blockDim.x
    const float lam_b = __ldg(&lam[b]);
    const float dec_b = __ldg(&dec[b]);
    const int   p     = __ldg(&perm[b]);

    const float oh  = __ldg(&onehot[b * C + c]);
    const float ohp = __ldg(&onehot[p * C + c]);
    const float label_mix = lam_b * oh + (1.0f - lam_b) * ohp;
    out_label[b * C + c] = dec_b * label_mix + (1.0f - dec_b) * oh;
}

extern "C" void kernel_launch(void* const* d_in, const int* in_sizes, int n_in,
                              void* d_out, int out_size)
{
    const float* wave   = (const float*)d_in[0];
    const float* onehot = (const float*)d_in[1];
    const float* lam    = (const float*)d_in[2];
    const int*   perm   = (const int*)  d_in[3];
    const float* dec    = (const float*)d_in[4];
    const int*   start  = (const int*)  d_in[5];

    float* out_wave  = (float*)d_out;
    float* out_label = out_wave + (size_t)B * L;

    dim3 block(256);
    dim3 grid((F4_PER_ROW + 255) / 256, B);   // (157, 128)
    cutmix_wave_kernel<<<grid, block>>>(wave, lam, perm, dec, start, out_wave);
    cutmix_label_kernel<<<B, C>>>(onehot, lam, perm, dec, out_label);
}

// round 3
// speedup vs baseline: 1.0078x; 1.0078x over previous
#include <cuda_runtime.h>
#include <cuda_bf16.h>
#include <cstdint>

// Cutmix:
//   wave  [B=128, L=160000] f32
//   onehot[B=128, C=128]    f32
//   lam   [B] f32, perm [B] i32, dec [B] f32, start [B] i32
// Output: wave_mix [B,L] followed by label_out [B,C], both f32, concatenated.
//
// Single fused kernel. Grid is (157, 128); CTA x=156 of each row has only 64
// wave-active threads (40000 = 156*256 + 64), so its threads 64..191 compute
// that row's 128 label outputs — no second launch.

static constexpr int B = 128;
static constexpr int L = 160000;
static constexpr int C = 128;
static constexpr int F4_PER_ROW = L / 4;            // 40000
static constexpr int GRID_X = (F4_PER_ROW + 255) / 256;   // 157

__global__ __launch_bounds__(256)
void cutmix_fused_kernel(const float* __restrict__ wave,
                         const float* __restrict__ onehot,
                         const float* __restrict__ lam,
                         const int*   __restrict__ perm,
                         const float* __restrict__ dec,
                         const int*   __restrict__ start,
                         float* __restrict__ out_wave,
                         float* __restrict__ out_label)
{
    const int b   = blockIdx.y;
    const int tid = threadIdx.x;
    const int j   = blockIdx.x * blockDim.x + tid;   // float4 index within row

    // Per-row scalars — uniform across the CTA.
    const float lam_b = __ldg(&lam[b]);
    const float dec_f = __ldg(&dec[b]);
    const int   p     = __ldg(&perm[b]);

    if (j < F4_PER_ROW) {
        const int  s      = __ldg(&start[b]);
        const bool active = (dec_f == 1.0f);
        // crop_len exactly as reference: ((1.0f - lam) * L) truncated to int32
        const int crop_len = (int)((1.0f - lam_b) * (float)L);
        const int e = s + crop_len;                  // crop window [s, e)

        const int pos = j * 4;
        const float4* __restrict__ own_row  = (const float4*)(wave + (size_t)b * L);
        const float4* __restrict__ perm_row = (const float4*)(wave + (size_t)p * L);
        float4* __restrict__ out_row        = (float4*)(out_wave + (size_t)b * L);

        const bool outside = !active || e <= pos || s >= pos + 4;
        const bool inside  = active && s <= pos && pos + 4 <= e;

        float4 v;
        if (outside) {
            v = own_row[j];                          // bulk path 1: plain copy
        } else if (inside) {
            v = perm_row[j];                         // bulk path 2: permuted copy
        } else {
            // boundary-straddling float4 (<=2 per row): per-element select
            const float4 a = own_row[j];
            const float4 m = perm_row[j];
            v.x = (pos + 0 >= s && pos + 0 < e) ? m.x : a.x;
            v.y = (pos + 1 >= s && pos + 1 < e) ? m.y : a.y;
            v.z = (pos + 2 >= s && pos + 2 < e) ? m.z : a.z;
            v.w = (pos + 3 >= s && pos + 3 < e) ? m.w : a.w;
        }
        // Streaming store: output is never re-read; keep L2 for `wave`
        // (the perm-row gather re-reads it).
        __stcs(&out_row[j], v);
    } else if (blockIdx.x == GRID_X - 1 && tid >= 64 && tid < 64 + C) {
        // Label mix for row b, column c — runs on this row's idle tail threads.
        const int c = tid - 64;
        const float oh  = __ldg(&onehot[b * C + c]);
        const float ohp = __ldg(&onehot[p * C + c]);
        const float label_mix = lam_b * oh + (1.0f - lam_b) * ohp;
        out_label[b * C + c] = dec_f * label_mix + (1.0f - dec_f) * oh;
    }
}

extern "C" void kernel_launch(void* const* d_in, const int* in_sizes, int n_in,
                              void* d_out, int out_size)
{
    const float* wave   = (const float*)d_in[0];
    const float* onehot = (const float*)d_in[1];
    const float* lam    = (const float*)d_in[2];
    const int*   perm   = (const int*)  d_in[3];
    const float* dec    = (const float*)d_in[4];
    const int*   start  = (const int*)  d_in[5];

    float* out_wave  = (float*)d_out;
    float* out_label = out_wave + (size_t)B * L;

    dim3 block(256);
    dim3 grid(GRID_X, B);                            // (157, 128)
    cutmix_fused_kernel<<<grid, block>>>(wave, onehot, lam, perm, dec, start,
                                         out_wave, out_label);
}